// round 16
// baseline (speedup 1.0000x reference)
#include <cuda_runtime.h>
#include <cuda_bf16.h>

// Inputs (metadata order):
//   d_in[0] x                     float32 [2048]
//   d_in[1] y                     float32 [2048]
//   d_in[2] post_order_expression int32   [15]
//   d_in[3] post_level_map        int32   [15]
//   d_in[4] is_operator           bool    [5]
//   d_in[5] parameters            float32 [15,3]
// Output: float32 [D1, D2] row-major, out[i*D2 + j] = K(x[i], y[j])

#define NUM_ATOMS 3
#define MAX_NODES 15
#define EPSX 1e-6f
#define LOG2E 1.4426950408889634f
#define PI_F 3.14159265358979f
#define ROWS 8
#define THREADS 512

// Raw hardware approximations — single MUFU op each.
__device__ __forceinline__ float ex2_fast(float x) {
    float r; asm("ex2.approx.ftz.f32 %0, %1;" : "=f"(r) : "f"(x)); return r;
}
__device__ __forceinline__ float sin_fast(float x) {
    float r; asm("sin.approx.ftz.f32 %0, %1;" : "=f"(r) : "f"(x)); return r;
}

// Generic-path compile (thread 0 -> shared). Only runs on the fallback path.
__device__ __forceinline__ void compile_prog(const int* __restrict__ pe,
                                             const int* __restrict__ pl,
                                             const float* __restrict__ params,
                                             int* s_op, float4* s_c, int* s_meta) {
    int na = 0;
    for (int i = 0; i < MAX_NODES; ++i) {
        int v = pe[i];
        if (v < 0) continue;
        float4 c = make_float4(0.f, 0.f, 0.f, 0.f);
        if (v < NUM_ATOMS) {
            int lvl = pl[i];
            float p0 = params[3 * lvl + 0];
            float p1 = params[3 * lvl + 1];
            float p2 = params[3 * lvl + 2];
            float p0s = p0 * p0;
            float p1s = p1 * p1;
            if (v == 0) {                 // rbf
                c.x = p0s;
                c.y = __fdividef(-0.5f * LOG2E, p1s + EPSX);
            } else if (v == 1) {          // linear
                c.x = p0s;
                c.y = p1s;
            } else {                      // periodic
                c.x = p0s;
                c.y = __fdividef(-2.0f * LOG2E, p1s + EPSX);
                c.z = __fdividef(PI_F, p2 * p2 + 1.0f);   // pi / period
            }
        }
        s_op[na] = v;
        s_c[na]  = c;
        ++na;
    }
    s_meta[0] = na;
}

// ---------------------------------------------------------------------------
// Fused kernel: ROWS=8 rows/block, 512 threads -> 256 blocks (the measured
// optimum block count) with 32 warps/SM resident (2 blocks x 16 warps) —
// double R14's warp coverage at identical block-tax. Warp-parallel compile:
// lane l owns node l; ballot fingerprints; shfl broadcasts the 9 constants.
// Fast path per thread: 1 float4 of y x 8 rows = 32 elements, batched MUFU
// phases per row. MUFU.SIN direct: |d * pi/period| < 26 (in range).
// ---------------------------------------------------------------------------
__global__ void __launch_bounds__(THREADS, 2)
tree_fused_kernel(const float* __restrict__ x,
                  const float* __restrict__ y,
                  float* __restrict__ out,
                  int d1, int d2,
                  const int* __restrict__ pe,
                  const int* __restrict__ pl,
                  const float* __restrict__ params) {
    const int t    = threadIdx.x;
    const int lane = t & 31;
    const int qcols = d2 >> 2;
    const int i0   = blockIdx.x * ROWS;

    // ---- warp-parallel compile ----
    int v = -1;
    float cx = 0.f, cy = 0.f, cz = 0.f, cw = 0.f;
    if (lane < MAX_NODES) v = __ldg(pe + lane);

    const int want7[7] = {0, 1, 4, 2, 0, 3, 3};
    bool okl = (lane < 7) ? (v == want7[lane])
             : (lane < MAX_NODES ? (v < 0) : true);
    const unsigned mask = __ballot_sync(0xffffffffu, okl);
    const bool fast = (mask == 0xffffffffu);

    if (lane < MAX_NODES && v >= 0 && v < NUM_ATOMS) {
        int   lvl = __ldg(pl + lane);
        float p0  = __ldg(params + 3 * lvl + 0);
        float p1  = __ldg(params + 3 * lvl + 1);
        float p2  = __ldg(params + 3 * lvl + 2);
        float p0s = p0 * p0;
        float p1s = p1 * p1;
        if (v == 0) {                     // rbf
            cx = p0s;
            cy = __fdividef(-0.5f * LOG2E, p1s + EPSX);
            cw = __log2f(p0s);
        } else if (v == 1) {              // linear
            cx = p0s;
            cy = p1s;
        } else {                          // periodic
            cx = p0s;
            cy = __fdividef(-2.0f * LOG2E, p1s + EPSX);
            cz = __fdividef(PI_F, p2 * p2 + 1.0f);
            cw = __log2f(p0s);
        }
    }

    const float4* y4p = reinterpret_cast<const float4*>(y);

    if (fast && qcols == (int)blockDim.x && i0 + ROWS <= d1) {
        const float aY = __shfl_sync(0xffffffffu, cy, 0);
        const float aW = __shfl_sync(0xffffffffu, cw, 0);
        const float bX = __shfl_sync(0xffffffffu, cx, 1);
        const float bY = __shfl_sync(0xffffffffu, cy, 1);
        const float pY = __shfl_sync(0xffffffffu, cy, 3);
        const float pZ = __shfl_sync(0xffffffffu, cz, 3);   // pi/period
        const float pW = __shfl_sync(0xffffffffu, cw, 3);
        const float dY = __shfl_sync(0xffffffffu, cy, 4);
        const float dW = __shfl_sync(0xffffffffu, cw, 4);

        const float4 y4 = __ldg(y4p + t);
        const float yv[4] = {y4.x, y4.y, y4.z, y4.w};

#pragma unroll
        for (int rr = 0; rr < ROWS; ++rr) {
            const float xi   = __ldg(x + i0 + rr);
            const float bXxi = bX * xi;              // hoisted per row

            // Phase 1: all FMA-pipe feeder args (independent per element)
            float a1[4], a4[4], hh[4], k2[4];
#pragma unroll
            for (int l = 0; l < 4; ++l) {
                float yj  = yv[l];
                float d   = xi - yj;
                float d2s = d * d;
                a1[l] = fmaf(aY, d2s, aW);
                a4[l] = fmaf(dY, d2s, dW);
                hh[l] = d * pZ;
                k2[l] = fmaf(bXxi, yj, bY);
            }
            // Phase 2: independent SINs back-to-back
            float ss[4];
#pragma unroll
            for (int l = 0; l < 4; ++l) ss[l] = sin_fast(hh[l]);
            // Phase 3: independent EX2s (12 total)
            float k1[4], k3[4], k4[4];
#pragma unroll
            for (int l = 0; l < 4; ++l) k1[l] = ex2_fast(a1[l]);
#pragma unroll
            for (int l = 0; l < 4; ++l) k4[l] = ex2_fast(a4[l]);
#pragma unroll
            for (int l = 0; l < 4; ++l)
                k3[l] = ex2_fast(fmaf(pY * ss[l], ss[l], pW));
            // Phase 4: combine + store
            float r[4];
#pragma unroll
            for (int l = 0; l < 4; ++l)
                r[l] = (k4[l] + k3[l]) + k1[l] * k2[l];

            float4* o4p = reinterpret_cast<float4*>(out + (size_t)(i0 + rr) * d2);
            o4p[t] = make_float4(r[0], r[1], r[2], r[3]);
        }
        return;
    }

    // ---- generic interpreter fallback (uniform across the whole grid) ----
    __shared__ int    s_op[MAX_NODES];
    __shared__ float4 s_c[MAX_NODES];
    __shared__ int    s_meta[1];
    if (t == 0) compile_prog(pe, pl, params, s_op, s_c, s_meta);
    __syncthreads();

    const int n = s_meta[0];
    for (int rr = 0; rr < ROWS; ++rr) {
        const int i = i0 + rr;
        if (i >= d1) break;
        const float xi = __ldg(x + i);
        float4* o4p = reinterpret_cast<float4*>(out + (size_t)i * d2);
        for (int c = t; c < qcols; c += blockDim.x) {
            const float4 y4 = __ldg(y4p + c);
            float yv[4] = {y4.x, y4.y, y4.z, y4.w};
            float dx[4];
#pragma unroll
            for (int l = 0; l < 4; ++l) dx[l] = xi - yv[l];

            float st[4][4];
#pragma unroll
            for (int l = 0; l < 4; ++l) st[0][l] = 0.0f;
            int ptr = 0;
            for (int nn = 0; nn < n; ++nn) {
                const int    op = s_op[nn];
                const float4 cc = s_c[nn];
                if (op >= NUM_ATOMS) {
                    if (op == NUM_ATOMS) {
#pragma unroll
                        for (int l = 0; l < 4; ++l)
                            st[ptr - 2][l] = st[ptr - 1][l] + st[ptr - 2][l];
                    } else {
#pragma unroll
                        for (int l = 0; l < 4; ++l)
                            st[ptr - 2][l] = st[ptr - 1][l] * st[ptr - 2][l];
                    }
                    --ptr;
                } else if (op == 0) {
#pragma unroll
                    for (int l = 0; l < 4; ++l)
                        st[ptr][l] = cc.x * ex2_fast(cc.y * dx[l] * dx[l]);
                    ++ptr;
                } else if (op == 1) {
#pragma unroll
                    for (int l = 0; l < 4; ++l)
                        st[ptr][l] = fmaf(cc.x, xi * yv[l], cc.y);
                    ++ptr;
                } else {
#pragma unroll
                    for (int l = 0; l < 4; ++l) {
                        float s = sin_fast(dx[l] * cc.z);
                        st[ptr][l] = cc.x * ex2_fast(cc.y * s * s);
                    }
                    ++ptr;
                }
            }
            o4p[c] = make_float4(st[0][0], st[0][1], st[0][2], st[0][3]);
        }
    }
}

// Scalar fallback for d2 not divisible by 4 (not expected in this bench).
__global__ void tree_scalar_kernel(const float* __restrict__ x,
                                   const float* __restrict__ y,
                                   float* __restrict__ out,
                                   int d1, int d2,
                                   const int* __restrict__ pe,
                                   const int* __restrict__ pl,
                                   const float* __restrict__ params) {
    __shared__ int    s_op[MAX_NODES];
    __shared__ float4 s_c[MAX_NODES];
    __shared__ int    s_meta[1];
    if (threadIdx.x == 0) compile_prog(pe, pl, params, s_op, s_c, s_meta);
    __syncthreads();

    long idx = (long)blockIdx.x * blockDim.x + threadIdx.x;
    long total = (long)d1 * d2;
    if (idx >= total) return;
    int i = (int)(idx / d2);
    int j = (int)(idx - (long)i * d2);
    float xi = x[i], yj = y[j];
    float dx = xi - yj;
    float st[4] = {0.f, 0.f, 0.f, 0.f};
    int ptr = 0;
    const int n = s_meta[0];
    for (int nn = 0; nn < n; ++nn) {
        const int    op = s_op[nn];
        const float4 c  = s_c[nn];
        if (op >= NUM_ATOMS) {
            float v = (op == NUM_ATOMS) ? (st[ptr - 1] + st[ptr - 2])
                                        : (st[ptr - 1] * st[ptr - 2]);
            st[ptr - 2] = v; --ptr;
        } else if (op == 0) {
            st[ptr++] = c.x * ex2_fast(c.y * dx * dx);
        } else if (op == 1) {
            st[ptr++] = fmaf(c.x, xi * yj, c.y);
        } else {
            float s = sin_fast(dx * c.z);
            st[ptr++] = c.x * ex2_fast(c.y * s * s);
        }
    }
    out[idx] = st[0];
}

extern "C" void kernel_launch(void* const* d_in, const int* in_sizes, int n_in,
                              void* d_out, int out_size) {
    const float* x      = (const float*)d_in[0];
    const float* y      = (const float*)d_in[1];
    const int*   pe     = (const int*)d_in[2];
    const int*   pl     = (const int*)d_in[3];
    const float* params = (const float*)d_in[5];
    float*       out    = (float*)d_out;

    const int d1 = in_sizes[0];
    const int d2 = in_sizes[1];

    if ((d2 & 3) == 0 && (d1 % ROWS) == 0 && (d2 >> 2) == THREADS) {
        tree_fused_kernel<<<d1 / ROWS, THREADS>>>(x, y, out, d1, d2, pe, pl, params);
    } else {
        long total = (long)d1 * d2;
        int blocks = (int)((total + 255) / 256);
        tree_scalar_kernel<<<blocks, 256>>>(x, y, out, d1, d2, pe, pl, params);
    }
}

// round 17
// speedup vs baseline: 1.2620x; 1.2620x over previous
#include <cuda_runtime.h>
#include <cuda_bf16.h>

// Inputs (metadata order):
//   d_in[0] x                     float32 [2048]
//   d_in[1] y                     float32 [2048]
//   d_in[2] post_order_expression int32   [15]
//   d_in[3] post_level_map        int32   [15]
//   d_in[4] is_operator           bool    [5]
//   d_in[5] parameters            float32 [15,3]
// Output: float32 [D1, D2] row-major, out[i*D2 + j] = K(x[i], y[j])

#define NUM_ATOMS 3
#define MAX_NODES 15
#define EPSX 1e-6f
#define LOG2E 1.4426950408889634f
#define PI_F 3.14159265358979f
#define ROWS 8

// Raw hardware approximations — single MUFU op each.
__device__ __forceinline__ float ex2_fast(float x) {
    float r; asm("ex2.approx.ftz.f32 %0, %1;" : "=f"(r) : "f"(x)); return r;
}
__device__ __forceinline__ float sin_fast(float x) {
    float r; asm("sin.approx.ftz.f32 %0, %1;" : "=f"(r) : "f"(x)); return r;
}

// Generic-path compile (thread 0 -> shared). Only runs on the fallback path.
__device__ __forceinline__ void compile_prog(const int* __restrict__ pe,
                                             const int* __restrict__ pl,
                                             const float* __restrict__ params,
                                             int* s_op, float4* s_c, int* s_meta) {
    int na = 0;
    for (int i = 0; i < MAX_NODES; ++i) {
        int v = pe[i];
        if (v < 0) continue;
        float4 c = make_float4(0.f, 0.f, 0.f, 0.f);
        if (v < NUM_ATOMS) {
            int lvl = pl[i];
            float p0 = params[3 * lvl + 0];
            float p1 = params[3 * lvl + 1];
            float p2 = params[3 * lvl + 2];
            float p0s = p0 * p0;
            float p1s = p1 * p1;
            if (v == 0) {                 // rbf
                c.x = p0s;
                c.y = __fdividef(-0.5f * LOG2E, p1s + EPSX);
            } else if (v == 1) {          // linear
                c.x = p0s;
                c.y = p1s;
            } else {                      // periodic
                c.x = p0s;
                c.y = __fdividef(-2.0f * LOG2E, p1s + EPSX);
                c.z = __fdividef(PI_F, p2 * p2 + 1.0f);   // pi / period
            }
        }
        s_op[na] = v;
        s_c[na]  = c;
        ++na;
    }
    s_meta[0] = na;
}

// ---------------------------------------------------------------------------
// Fused kernel (best-measured configuration — R14, timed 8.67us):
// ROWS=8 rows/block, 256 threads -> 256 blocks, __launch_bounds__(256,4).
// Warp-parallel compile: lane l owns node l; ballot fingerprints; shfl
// broadcasts the 9 constants. Fast path per thread: 8 y values x 8 rows =
// 64 elements, batched MUFU phases per row (feeder FMAs -> 8 SINs -> 24
// EX2s -> combine). MUFU.SIN direct: |d * pi/period| < 26 (in range).
// ---------------------------------------------------------------------------
__global__ void __launch_bounds__(256, 4)
tree_fused_kernel(const float* __restrict__ x,
                  const float* __restrict__ y,
                  float* __restrict__ out,
                  int d1, int d2,
                  const int* __restrict__ pe,
                  const int* __restrict__ pl,
                  const float* __restrict__ params) {
    const int t    = threadIdx.x;
    const int lane = t & 31;
    const int qcols = d2 >> 2;
    const int i0   = blockIdx.x * ROWS;

    // ---- warp-parallel compile ----
    int v = -1;
    float cx = 0.f, cy = 0.f, cz = 0.f, cw = 0.f;
    if (lane < MAX_NODES) v = __ldg(pe + lane);

    const int want7[7] = {0, 1, 4, 2, 0, 3, 3};
    bool okl = (lane < 7) ? (v == want7[lane])
             : (lane < MAX_NODES ? (v < 0) : true);
    const unsigned mask = __ballot_sync(0xffffffffu, okl);
    const bool fast = (mask == 0xffffffffu);

    if (lane < MAX_NODES && v >= 0 && v < NUM_ATOMS) {
        int   lvl = __ldg(pl + lane);
        float p0  = __ldg(params + 3 * lvl + 0);
        float p1  = __ldg(params + 3 * lvl + 1);
        float p2  = __ldg(params + 3 * lvl + 2);
        float p0s = p0 * p0;
        float p1s = p1 * p1;
        if (v == 0) {                     // rbf
            cx = p0s;
            cy = __fdividef(-0.5f * LOG2E, p1s + EPSX);
            cw = __log2f(p0s);
        } else if (v == 1) {              // linear
            cx = p0s;
            cy = p1s;
        } else {                          // periodic
            cx = p0s;
            cy = __fdividef(-2.0f * LOG2E, p1s + EPSX);
            cz = __fdividef(PI_F, p2 * p2 + 1.0f);
            cw = __log2f(p0s);
        }
    }

    const float4* y4p = reinterpret_cast<const float4*>(y);

    if (fast && qcols == 2 * (int)blockDim.x && (i0 & 7) == 0 && i0 + ROWS <= d1) {
        const float aY = __shfl_sync(0xffffffffu, cy, 0);
        const float aW = __shfl_sync(0xffffffffu, cw, 0);
        const float bX = __shfl_sync(0xffffffffu, cx, 1);
        const float bY = __shfl_sync(0xffffffffu, cy, 1);
        const float pY = __shfl_sync(0xffffffffu, cy, 3);
        const float pZ = __shfl_sync(0xffffffffu, cz, 3);   // pi/period
        const float pW = __shfl_sync(0xffffffffu, cw, 3);
        const float dY = __shfl_sync(0xffffffffu, cy, 4);
        const float dW = __shfl_sync(0xffffffffu, cw, 4);

        const float4 xa = __ldg(reinterpret_cast<const float4*>(x + i0));
        const float4 xb = __ldg(reinterpret_cast<const float4*>(x + i0 + 4));
        const float  xr[ROWS] = {xa.x, xa.y, xa.z, xa.w, xb.x, xb.y, xb.z, xb.w};

        const float4 ya = __ldg(y4p + t);
        const float4 yb = __ldg(y4p + t + 256);
        const float yv[8] = {ya.x, ya.y, ya.z, ya.w, yb.x, yb.y, yb.z, yb.w};

#pragma unroll
        for (int rr = 0; rr < ROWS; ++rr) {
            const float xi   = xr[rr];
            const float bXxi = bX * xi;              // hoisted per row

            // Phase 1: all FMA-pipe feeder args (independent per element)
            float a1[8], a4[8], hh[8], k2[8];
#pragma unroll
            for (int l = 0; l < 8; ++l) {
                float yj  = yv[l];
                float d   = xi - yj;
                float d2s = d * d;
                a1[l] = fmaf(aY, d2s, aW);
                a4[l] = fmaf(dY, d2s, dW);
                hh[l] = d * pZ;
                k2[l] = fmaf(bXxi, yj, bY);
            }
            // Phase 2: 8 independent SINs back-to-back
            float ss[8];
#pragma unroll
            for (int l = 0; l < 8; ++l) ss[l] = sin_fast(hh[l]);
            // Phase 3: independent EX2s (24 total)
            float k1[8], k3[8], k4[8];
#pragma unroll
            for (int l = 0; l < 8; ++l) k1[l] = ex2_fast(a1[l]);
#pragma unroll
            for (int l = 0; l < 8; ++l) k4[l] = ex2_fast(a4[l]);
#pragma unroll
            for (int l = 0; l < 8; ++l)
                k3[l] = ex2_fast(fmaf(pY * ss[l], ss[l], pW));
            // Phase 4: combine + store
            float r[8];
#pragma unroll
            for (int l = 0; l < 8; ++l)
                r[l] = (k4[l] + k3[l]) + k1[l] * k2[l];

            float4* o4p = reinterpret_cast<float4*>(out + (size_t)(i0 + rr) * d2);
            o4p[t]       = make_float4(r[0], r[1], r[2], r[3]);
            o4p[t + 256] = make_float4(r[4], r[5], r[6], r[7]);
        }
        return;
    }

    // ---- generic interpreter fallback (uniform across the whole grid) ----
    __shared__ int    s_op[MAX_NODES];
    __shared__ float4 s_c[MAX_NODES];
    __shared__ int    s_meta[1];
    if (t == 0) compile_prog(pe, pl, params, s_op, s_c, s_meta);
    __syncthreads();

    const int n = s_meta[0];
    for (int rr = 0; rr < ROWS; ++rr) {
        const int i = i0 + rr;
        if (i >= d1) break;
        const float xi = __ldg(x + i);
        float4* o4p = reinterpret_cast<float4*>(out + (size_t)i * d2);
        for (int c = t; c < qcols; c += blockDim.x) {
            const float4 y4 = __ldg(y4p + c);
            float yv[4] = {y4.x, y4.y, y4.z, y4.w};
            float dx[4];
#pragma unroll
            for (int l = 0; l < 4; ++l) dx[l] = xi - yv[l];

            float st[4][4];
#pragma unroll
            for (int l = 0; l < 4; ++l) st[0][l] = 0.0f;
            int ptr = 0;
            for (int nn = 0; nn < n; ++nn) {
                const int    op = s_op[nn];
                const float4 cc = s_c[nn];
                if (op >= NUM_ATOMS) {
                    if (op == NUM_ATOMS) {
#pragma unroll
                        for (int l = 0; l < 4; ++l)
                            st[ptr - 2][l] = st[ptr - 1][l] + st[ptr - 2][l];
                    } else {
#pragma unroll
                        for (int l = 0; l < 4; ++l)
                            st[ptr - 2][l] = st[ptr - 1][l] * st[ptr - 2][l];
                    }
                    --ptr;
                } else if (op == 0) {
#pragma unroll
                    for (int l = 0; l < 4; ++l)
                        st[ptr][l] = cc.x * ex2_fast(cc.y * dx[l] * dx[l]);
                    ++ptr;
                } else if (op == 1) {
#pragma unroll
                    for (int l = 0; l < 4; ++l)
                        st[ptr][l] = fmaf(cc.x, xi * yv[l], cc.y);
                    ++ptr;
                } else {
#pragma unroll
                    for (int l = 0; l < 4; ++l) {
                        float s = sin_fast(dx[l] * cc.z);
                        st[ptr][l] = cc.x * ex2_fast(cc.y * s * s);
                    }
                    ++ptr;
                }
            }
            o4p[c] = make_float4(st[0][0], st[0][1], st[0][2], st[0][3]);
        }
    }
}

// Scalar fallback for d2 not divisible by 4 (not expected in this bench).
__global__ void tree_scalar_kernel(const float* __restrict__ x,
                                   const float* __restrict__ y,
                                   float* __restrict__ out,
                                   int d1, int d2,
                                   const int* __restrict__ pe,
                                   const int* __restrict__ pl,
                                   const float* __restrict__ params) {
    __shared__ int    s_op[MAX_NODES];
    __shared__ float4 s_c[MAX_NODES];
    __shared__ int    s_meta[1];
    if (threadIdx.x == 0) compile_prog(pe, pl, params, s_op, s_c, s_meta);
    __syncthreads();

    long idx = (long)blockIdx.x * blockDim.x + threadIdx.x;
    long total = (long)d1 * d2;
    if (idx >= total) return;
    int i = (int)(idx / d2);
    int j = (int)(idx - (long)i * d2);
    float xi = x[i], yj = y[j];
    float dx = xi - yj;
    float st[4] = {0.f, 0.f, 0.f, 0.f};
    int ptr = 0;
    const int n = s_meta[0];
    for (int nn = 0; nn < n; ++nn) {
        const int    op = s_op[nn];
        const float4 c  = s_c[nn];
        if (op >= NUM_ATOMS) {
            float v = (op == NUM_ATOMS) ? (st[ptr - 1] + st[ptr - 2])
                                        : (st[ptr - 1] * st[ptr - 2]);
            st[ptr - 2] = v; --ptr;
        } else if (op == 0) {
            st[ptr++] = c.x * ex2_fast(c.y * dx * dx);
        } else if (op == 1) {
            st[ptr++] = fmaf(c.x, xi * yj, c.y);
        } else {
            float s = sin_fast(dx * c.z);
            st[ptr++] = c.x * ex2_fast(c.y * s * s);
        }
    }
    out[idx] = st[0];
}

extern "C" void kernel_launch(void* const* d_in, const int* in_sizes, int n_in,
                              void* d_out, int out_size) {
    const float* x      = (const float*)d_in[0];
    const float* y      = (const float*)d_in[1];
    const int*   pe     = (const int*)d_in[2];
    const int*   pl     = (const int*)d_in[3];
    const float* params = (const float*)d_in[5];
    float*       out    = (float*)d_out;

    const int d1 = in_sizes[0];
    const int d2 = in_sizes[1];

    if ((d2 & 3) == 0 && (d1 % ROWS) == 0 && (d2 >> 2) == 512) {
        tree_fused_kernel<<<d1 / ROWS, 256>>>(x, y, out, d1, d2, pe, pl, params);
    } else {
        long total = (long)d1 * d2;
        int blocks = (int)((total + 255) / 256);
        tree_scalar_kernel<<<blocks, 256>>>(x, y, out, d1, d2, pe, pl, params);
    }
}